// round 4
// baseline (speedup 1.0000x reference)
#include <cuda_runtime.h>
#include <math.h>

#define BB   2
#define SEQ  2048
#define CH   768
#define NH   12
#define HD   64
#define MROWS (BB*SEQ)      // 4096
#define QKVN  (3*CH)        // 2304
#define LSTR  65            // padded smem stride for flash kernel

// Scratch (device globals: allocation-free rule)
__device__ float g_q[BB*NH*SEQ*HD];
__device__ float g_k[BB*NH*SEQ*HD];
__device__ float g_v[BB*NH*SEQ*HD];
__device__ float g_ctx[MROWS*CH];

// ---------------------------------------------------------------------------
// QKV GEMM: y[m,c] = sum_k x[m,k] * w_qkv[c,k]; epilogue scatters into
// head-major q/k/v with scale + interleaved RoPE fused for q,k.
// Tile 64x64, TK=16, 256 threads, 4x4 per-thread register block.
// ---------------------------------------------------------------------------
__global__ __launch_bounds__(256) void qkv_gemm_kernel(
    const float* __restrict__ X, const float* __restrict__ W)
{
    __shared__ float As[16][64];   // As[k][m]
    __shared__ float Bs[16][64];   // Bs[k][c]
    const int tid = threadIdx.x;
    const int tx = tid & 15, ty = tid >> 4;
    const int m0 = blockIdx.y * 64, c0 = blockIdx.x * 64;
    const int lrow = tid >> 2;
    const int lk   = (tid & 3) * 4;

    float acc[4][4];
#pragma unroll
    for (int i = 0; i < 4; i++)
#pragma unroll
        for (int j = 0; j < 4; j++) acc[i][j] = 0.f;

    for (int k0 = 0; k0 < CH; k0 += 16) {
        float4 av = *(const float4*)&X[(m0 + lrow) * CH + k0 + lk];
        float4 wv = *(const float4*)&W[(c0 + lrow) * CH + k0 + lk];
        __syncthreads();
        As[lk+0][lrow] = av.x; As[lk+1][lrow] = av.y;
        As[lk+2][lrow] = av.z; As[lk+3][lrow] = av.w;
        Bs[lk+0][lrow] = wv.x; Bs[lk+1][lrow] = wv.y;
        Bs[lk+2][lrow] = wv.z; Bs[lk+3][lrow] = wv.w;
        __syncthreads();
#pragma unroll
        for (int kk = 0; kk < 16; kk++) {
            float4 a4 = *(const float4*)&As[kk][ty * 4];
            float4 b4 = *(const float4*)&Bs[kk][tx * 4];
            float a[4] = {a4.x, a4.y, a4.z, a4.w};
            float b[4] = {b4.x, b4.y, b4.z, b4.w};
#pragma unroll
            for (int i = 0; i < 4; i++)
#pragma unroll
                for (int j = 0; j < 4; j++)
                    acc[i][j] = fmaf(a[i], b[j], acc[i][j]);
        }
    }

    // Epilogue: thread owns cols cc..cc+3 (cc even => 2 full RoPE pairs)
    const int cc    = c0 + tx * 4;
    const int which = cc / CH;           // 0=q, 1=k, 2=v
    const int h     = (cc % CH) / HD;
    const int dd    = cc % HD;           // multiple of 4
    float* dst = (which == 0) ? g_q : (which == 1) ? g_k : g_v;
    const float sc = (which == 0) ? 0.125f : 1.0f;   // d^-0.5 = 64^-0.5

    const float inv0 = powf(10000.f, -((float)dd)       / 64.f);
    const float inv1 = powf(10000.f, -((float)(dd + 2)) / 64.f);

#pragma unroll
    for (int ii = 0; ii < 4; ii++) {
        int m = m0 + ty * 4 + ii;
        int b = m / SEQ, n = m % SEQ;
        float4 r;
        if (which == 2) {
            r = make_float4(acc[ii][0], acc[ii][1], acc[ii][2], acc[ii][3]);
        } else {
            float fn = (float)n;
            float s0, c0r, s1, c1r;
            sincosf(fn * inv0, &s0, &c0r);
            sincosf(fn * inv1, &s1, &c1r);
            float x0 = acc[ii][0] * sc, x1 = acc[ii][1] * sc;
            float x2 = acc[ii][2] * sc, x3 = acc[ii][3] * sc;
            r.x = x0 * c0r - x1 * s0;
            r.y = x1 * c0r + x0 * s0;
            r.z = x2 * c1r - x3 * s1;
            r.w = x3 * c1r + x2 * s1;
        }
        *(float4*)&dst[((b * NH + h) * SEQ + n) * HD + dd] = r;
    }
}

// ---------------------------------------------------------------------------
// Flash attention: one block per (b*h, 64-query tile). Online softmax, row
// stats in registers, P staged through smem for the P.V GEMM.
// ---------------------------------------------------------------------------
__global__ __launch_bounds__(256) void flash_kernel()
{
    extern __shared__ float sm[];
    float* Qs = sm;                  // [64][LSTR]
    float* Ks = sm + 64 * LSTR;
    float* Vs = sm + 2 * 64 * LSTR;
    float* Ps = sm + 3 * 64 * LSTR;

    const int tid = threadIdx.x;
    const int tx = tid & 15, ty = tid >> 4;
    const int bh = blockIdx.y;
    const int q0 = blockIdx.x * 64;

    const float* qb = g_q + (bh * SEQ + q0) * HD;
    const float* kb = g_k + bh * SEQ * HD;
    const float* vb = g_v + bh * SEQ * HD;

    // load Q tile
    for (int f = tid; f < 1024; f += 256) {
        int r = f >> 4, c = (f & 15) * 4;
        float4 v = *(const float4*)&qb[r * HD + c];
        Qs[r * LSTR + c + 0] = v.x; Qs[r * LSTR + c + 1] = v.y;
        Qs[r * LSTR + c + 2] = v.z; Qs[r * LSTR + c + 3] = v.w;
    }

    float mi[4], li[4], o[4][4];
#pragma unroll
    for (int i = 0; i < 4; i++) {
        mi[i] = -1e30f; li[i] = 0.f;
#pragma unroll
        for (int j = 0; j < 4; j++) o[i][j] = 0.f;
    }

    for (int j0 = 0; j0 < SEQ; j0 += 64) {
        __syncthreads();   // protect Ks/Vs/Ps from previous iteration's readers
        for (int f = tid; f < 1024; f += 256) {
            int r = f >> 4, c = (f & 15) * 4;
            float4 kv = *(const float4*)&kb[(j0 + r) * HD + c];
            float4 vv = *(const float4*)&vb[(j0 + r) * HD + c];
            Ks[r * LSTR + c + 0] = kv.x; Ks[r * LSTR + c + 1] = kv.y;
            Ks[r * LSTR + c + 2] = kv.z; Ks[r * LSTR + c + 3] = kv.w;
            Vs[r * LSTR + c + 0] = vv.x; Vs[r * LSTR + c + 1] = vv.y;
            Vs[r * LSTR + c + 2] = vv.z; Vs[r * LSTR + c + 3] = vv.w;
        }
        __syncthreads();

        // S = Q . K^T (4x4 per thread)
        float s[4][4];
#pragma unroll
        for (int i = 0; i < 4; i++)
#pragma unroll
            for (int j = 0; j < 4; j++) s[i][j] = 0.f;

#pragma unroll 8
        for (int kk = 0; kk < HD; kk++) {
            float a[4], b[4];
#pragma unroll
            for (int i = 0; i < 4; i++) a[i] = Qs[(ty * 4 + i) * LSTR + kk];
#pragma unroll
            for (int j = 0; j < 4; j++) b[j] = Ks[(tx * 4 + j) * LSTR + kk];
#pragma unroll
            for (int i = 0; i < 4; i++)
#pragma unroll
                for (int j = 0; j < 4; j++)
                    s[i][j] = fmaf(a[i], b[j], s[i][j]);
        }

        // online softmax per row
#pragma unroll
        for (int i = 0; i < 4; i++) {
            float mx = fmaxf(fmaxf(s[i][0], s[i][1]), fmaxf(s[i][2], s[i][3]));
#pragma unroll
            for (int msk = 8; msk; msk >>= 1)
                mx = fmaxf(mx, __shfl_xor_sync(0xffffffffu, mx, msk));
            float mnew = fmaxf(mi[i], mx);
            float p[4], sum = 0.f;
#pragma unroll
            for (int j = 0; j < 4; j++) { p[j] = __expf(s[i][j] - mnew); sum += p[j]; }
#pragma unroll
            for (int msk = 8; msk; msk >>= 1)
                sum += __shfl_xor_sync(0xffffffffu, sum, msk);
            float alpha = __expf(mi[i] - mnew);
            li[i] = li[i] * alpha + sum;
            mi[i] = mnew;
#pragma unroll
            for (int j = 0; j < 4; j++) o[i][j] *= alpha;
#pragma unroll
            for (int j = 0; j < 4; j++)
                Ps[(ty * 4 + i) * LSTR + tx * 4 + j] = p[j];
        }
        __syncthreads();

        // O += P . V
#pragma unroll 8
        for (int j = 0; j < 64; j++) {
            float a[4], b[4];
#pragma unroll
            for (int i = 0; i < 4; i++) a[i] = Ps[(ty * 4 + i) * LSTR + j];
#pragma unroll
            for (int c = 0; c < 4; c++) b[c] = Vs[j * LSTR + tx * 4 + c];
#pragma unroll
            for (int i = 0; i < 4; i++)
#pragma unroll
                for (int c = 0; c < 4; c++)
                    o[i][c] = fmaf(a[i], b[c], o[i][c]);
        }
    }

    // write ctx in [B,N,C] layout (transpose back to token-major)
    const int b = bh / NH, h = bh % NH;
#pragma unroll
    for (int i = 0; i < 4; i++) {
        int n = q0 + ty * 4 + i;
        float inv = 1.f / li[i];
        float4 r = make_float4(o[i][0] * inv, o[i][1] * inv,
                               o[i][2] * inv, o[i][3] * inv);
        *(float4*)&g_ctx[(b * SEQ + n) * CH + h * HD + tx * 4] = r;
    }
}

// ---------------------------------------------------------------------------
// Output projection: out[m,c] = sum_k ctx[m,k] * w_proj[c,k] + b_proj[c]
// ---------------------------------------------------------------------------
__global__ __launch_bounds__(256) void proj_gemm_kernel(
    const float* __restrict__ W, const float* __restrict__ bias,
    float* __restrict__ out)
{
    __shared__ float As[16][64];
    __shared__ float Bs[16][64];
    const int tid = threadIdx.x;
    const int tx = tid & 15, ty = tid >> 4;
    const int m0 = blockIdx.y * 64, c0 = blockIdx.x * 64;
    const int lrow = tid >> 2;
    const int lk   = (tid & 3) * 4;

    float acc[4][4];
#pragma unroll
    for (int i = 0; i < 4; i++)
#pragma unroll
        for (int j = 0; j < 4; j++) acc[i][j] = 0.f;

    for (int k0 = 0; k0 < CH; k0 += 16) {
        float4 av = *(const float4*)&g_ctx[(m0 + lrow) * CH + k0 + lk];
        float4 wv = *(const float4*)&W[(c0 + lrow) * CH + k0 + lk];
        __syncthreads();
        As[lk+0][lrow] = av.x; As[lk+1][lrow] = av.y;
        As[lk+2][lrow] = av.z; As[lk+3][lrow] = av.w;
        Bs[lk+0][lrow] = wv.x; Bs[lk+1][lrow] = wv.y;
        Bs[lk+2][lrow] = wv.z; Bs[lk+3][lrow] = wv.w;
        __syncthreads();
#pragma unroll
        for (int kk = 0; kk < 16; kk++) {
            float4 a4 = *(const float4*)&As[kk][ty * 4];
            float4 b4 = *(const float4*)&Bs[kk][tx * 4];
            float a[4] = {a4.x, a4.y, a4.z, a4.w};
            float b[4] = {b4.x, b4.y, b4.z, b4.w};
#pragma unroll
            for (int i = 0; i < 4; i++)
#pragma unroll
                for (int j = 0; j < 4; j++)
                    acc[i][j] = fmaf(a[i], b[j], acc[i][j]);
        }
    }

    const int c = c0 + tx * 4;
    float4 bv = *(const float4*)&bias[c];
#pragma unroll
    for (int ii = 0; ii < 4; ii++) {
        int m = m0 + ty * 4 + ii;
        float4 r = make_float4(acc[ii][0] + bv.x, acc[ii][1] + bv.y,
                               acc[ii][2] + bv.z, acc[ii][3] + bv.w);
        *(float4*)&out[m * CH + c] = r;
    }
}

// ---------------------------------------------------------------------------
extern "C" void kernel_launch(void* const* d_in, const int* in_sizes, int n_in,
                              void* d_out, int out_size)
{
    const float* x      = (const float*)d_in[0];
    const float* w_qkv  = (const float*)d_in[1];
    const float* w_proj = (const float*)d_in[2];
    const float* b_proj = (const float*)d_in[3];
    float* out = (float*)d_out;

    const int flash_smem = 4 * 64 * LSTR * (int)sizeof(float);  // 66560 B
    cudaFuncSetAttribute(flash_kernel,
                         cudaFuncAttributeMaxDynamicSharedMemorySize, flash_smem);

    dim3 g1(QKVN / 64, MROWS / 64);   // 36 x 64
    qkv_gemm_kernel<<<g1, 256>>>(x, w_qkv);

    dim3 g2(SEQ / 64, BB * NH);       // 32 x 24
    flash_kernel<<<g2, 256, flash_smem>>>();

    dim3 g3(CH / 64, MROWS / 64);     // 12 x 64
    proj_gemm_kernel<<<g3, 256>>>(w_proj, b_proj, out);
}

// round 5
// speedup vs baseline: 1.1837x; 1.1837x over previous
#include <cuda_runtime.h>
#include <math.h>

#define BB   2
#define SEQ  2048
#define CH   768
#define NH   12
#define HD   64
#define MROWS (BB*SEQ)      // 4096
#define QKVN  (3*CH)        // 2304

// Scratch (device globals: allocation-free rule)
__device__ float g_q[BB*NH*SEQ*HD];
__device__ float g_k[BB*NH*SEQ*HD];
__device__ float g_v[BB*NH*SEQ*HD];
__device__ float g_ctx[MROWS*CH];

// ---------------------------------------------------------------------------
// GEMM core: 128x128 tile, BK=32, 256 threads, 8x8 per-thread register tile.
// Smem layout: row-major [128][32] with XOR granule swizzle so that the
// 16-row-strided fragment loads are bank-conflict-free. A-frag loads are
// warp-broadcast (2 distinct addrs/warp).
// ---------------------------------------------------------------------------

#define GEMM_MAINLOOP(APTR, BPTR, KDIM)                                       \
    float acc[8][8];                                                          \
    _Pragma("unroll")                                                         \
    for (int i = 0; i < 8; i++)                                               \
        _Pragma("unroll")                                                     \
        for (int j = 0; j < 8; j++) acc[i][j] = 0.f;                          \
    for (int k0 = 0; k0 < (KDIM); k0 += 32) {                                 \
        float4 xa[4], wb[4];                                                  \
        _Pragma("unroll")                                                     \
        for (int t = 0; t < 4; t++) {                                         \
            int f = tid + t * 256;                                            \
            int r = f >> 3, g = f & 7;                                        \
            xa[t] = *(const float4*)&(APTR)[(m0 + r) * (KDIM) + k0 + g * 4];  \
            wb[t] = *(const float4*)&(BPTR)[(c0 + r) * (KDIM) + k0 + g * 4];  \
        }                                                                     \
        __syncthreads();                                                      \
        _Pragma("unroll")                                                     \
        for (int t = 0; t < 4; t++) {                                         \
            int f = tid + t * 256;                                            \
            int r = f >> 3, g = f & 7;                                        \
            int sg = g ^ ((r >> 3) & 7);                                      \
            *(float4*)&As[r * 32 + sg * 4] = xa[t];                           \
            *(float4*)&Bs[r * 32 + sg * 4] = wb[t];                           \
        }                                                                     \
        __syncthreads();                                                      \
        _Pragma("unroll")                                                     \
        for (int G = 0; G < 8; G++) {                                         \
            float4 bf[8];                                                     \
            _Pragma("unroll")                                                 \
            for (int jj = 0; jj < 8; jj++)                                    \
                bf[jj] = *(const float4*)&Bs[(tx * 8 + jj) * 32 +             \
                                             ((G ^ (tx & 7)) << 2)];          \
            _Pragma("unroll")                                                 \
            for (int i = 0; i < 8; i++) {                                     \
                float4 a = *(const float4*)&As[(ty * 8 + i) * 32 +            \
                                               ((G ^ (ty & 7)) << 2)];        \
                _Pragma("unroll")                                             \
                for (int jj = 0; jj < 8; jj++) {                              \
                    acc[i][jj] = fmaf(a.x, bf[jj].x, acc[i][jj]);             \
                    acc[i][jj] = fmaf(a.y, bf[jj].y, acc[i][jj]);             \
                    acc[i][jj] = fmaf(a.z, bf[jj].z, acc[i][jj]);             \
                    acc[i][jj] = fmaf(a.w, bf[jj].w, acc[i][jj]);             \
                }                                                             \
            }                                                                 \
        }                                                                     \
    }

// ---------------------------------------------------------------------------
// QKV GEMM: y[m,c] = sum_k x[m,k]*w_qkv[c,k]; epilogue fuses scale + RoPE
// and scatters into head-major q/k/v. Thread owns 8 consecutive cols = 4
// complete rotation pairs (never crosses threads).
// ---------------------------------------------------------------------------
__global__ __launch_bounds__(256, 2) void qkv_gemm_kernel(
    const float* __restrict__ X, const float* __restrict__ W)
{
    __shared__ float As[128 * 32];
    __shared__ float Bs[128 * 32];
    const int tid = threadIdx.x;
    const int tx = tid & 15, ty = tid >> 4;
    const int m0 = blockIdx.y * 128, c0 = blockIdx.x * 128;

    GEMM_MAINLOOP(X, W, CH)

    const int cc    = c0 + tx * 8;
    const int which = cc / CH;            // 0=q, 1=k, 2=v
    const int h     = (cc % CH) / HD;
    const int dd    = cc % HD;            // multiple of 8
    float* dst = (which == 0) ? g_q : (which == 1) ? g_k : g_v;
    const float sc = (which == 0) ? 0.125f : 1.0f;   // 64^-0.5

    float invf[4];
#pragma unroll
    for (int p = 0; p < 4; p++)
        invf[p] = powf(10000.f, -((float)(dd + 2 * p)) / 64.f);

#pragma unroll
    for (int i = 0; i < 8; i++) {
        int m = m0 + ty * 8 + i;
        int b = m / SEQ, n = m % SEQ;
        float out[8];
        if (which == 2) {
#pragma unroll
            for (int j = 0; j < 8; j++) out[j] = acc[i][j];
        } else {
            float fn = (float)n;
#pragma unroll
            for (int p = 0; p < 4; p++) {
                float s, c;
                sincosf(fn * invf[p], &s, &c);
                float x0 = acc[i][2 * p]     * sc;
                float x1 = acc[i][2 * p + 1] * sc;
                out[2 * p]     = x0 * c - x1 * s;
                out[2 * p + 1] = x1 * c + x0 * s;
            }
        }
        float* base = &dst[((b * NH + h) * SEQ + n) * HD + dd];
        *(float4*)base       = make_float4(out[0], out[1], out[2], out[3]);
        *(float4*)(base + 4) = make_float4(out[4], out[5], out[6], out[7]);
    }
}

// ---------------------------------------------------------------------------
// Flash attention: block = (b*h, 128-query tile), 256 threads, 8x4 per-thread
// S tile. K stored with XOR granule swizzle for conflict-free strided loads.
// Online softmax row stats in registers; P staged via smem for P.V.
// ---------------------------------------------------------------------------
__global__ __launch_bounds__(256, 2) void flash_kernel()
{
    extern __shared__ float sm[];
    float* Qs = sm;                    // [128][64]
    float* Ks = sm + 128 * 64;         // [64][64] swizzled
    float* Vs = sm + 128 * 64 + 64 * 64;
    float* Ps = sm + 128 * 64 + 2 * 64 * 64;   // [128][64]

    const int tid = threadIdx.x;
    const int tx = tid & 15, ty = tid >> 4;
    const int bh = blockIdx.y;
    const int q0 = blockIdx.x * 128;

    const float* qb = g_q + (bh * SEQ + q0) * HD;
    const float* kb = g_k + bh * SEQ * HD;
    const float* vb = g_v + bh * SEQ * HD;

    // load Q tile (linear layout)
#pragma unroll
    for (int t = 0; t < 8; t++) {
        int f = tid + t * 256;
        int r = f >> 4, c4 = f & 15;
        *(float4*)&Qs[r * 64 + c4 * 4] = *(const float4*)&qb[r * HD + c4 * 4];
    }

    float mi[8], li[8], o[8][4];
#pragma unroll
    for (int i = 0; i < 8; i++) {
        mi[i] = -1e30f; li[i] = 0.f;
#pragma unroll
        for (int j = 0; j < 4; j++) o[i][j] = 0.f;
    }

    for (int j0 = 0; j0 < SEQ; j0 += 64) {
        __syncthreads();   // previous tile's Ps/Vs readers done
#pragma unroll
        for (int t = 0; t < 4; t++) {
            int f = tid + t * 256;
            int r = f >> 4, c4 = f & 15;
            // K swizzled, V linear
            *(float4*)&Ks[r * 64 + ((c4 ^ ((r >> 2) & 15)) << 2)] =
                *(const float4*)&kb[(j0 + r) * HD + c4 * 4];
            *(float4*)&Vs[r * 64 + c4 * 4] =
                *(const float4*)&vb[(j0 + r) * HD + c4 * 4];
        }
        __syncthreads();

        // S = Q . K^T : 8x4 per thread, vectorized over k (granules of 4)
        float s[8][4];
#pragma unroll
        for (int i = 0; i < 8; i++)
#pragma unroll
            for (int j = 0; j < 4; j++) s[i][j] = 0.f;

#pragma unroll
        for (int G = 0; G < 16; G++) {
            float4 bf[4];
#pragma unroll
            for (int j = 0; j < 4; j++)
                bf[j] = *(const float4*)&Ks[(tx * 4 + j) * 64 + ((G ^ tx) << 2)];
#pragma unroll
            for (int i = 0; i < 8; i++) {
                float4 a = *(const float4*)&Qs[(ty * 8 + i) * 64 + (G << 2)];
#pragma unroll
                for (int j = 0; j < 4; j++) {
                    s[i][j] = fmaf(a.x, bf[j].x, s[i][j]);
                    s[i][j] = fmaf(a.y, bf[j].y, s[i][j]);
                    s[i][j] = fmaf(a.z, bf[j].z, s[i][j]);
                    s[i][j] = fmaf(a.w, bf[j].w, s[i][j]);
                }
            }
        }

        // online softmax (row reductions over the 16-lane tx group)
#pragma unroll
        for (int i = 0; i < 8; i++) {
            float mx = fmaxf(fmaxf(s[i][0], s[i][1]), fmaxf(s[i][2], s[i][3]));
#pragma unroll
            for (int msk = 8; msk; msk >>= 1)
                mx = fmaxf(mx, __shfl_xor_sync(0xffffffffu, mx, msk));
            float mnew = fmaxf(mi[i], mx);
            float4 p;
            p.x = __expf(s[i][0] - mnew);
            p.y = __expf(s[i][1] - mnew);
            p.z = __expf(s[i][2] - mnew);
            p.w = __expf(s[i][3] - mnew);
            float sum = p.x + p.y + p.z + p.w;
#pragma unroll
            for (int msk = 8; msk; msk >>= 1)
                sum += __shfl_xor_sync(0xffffffffu, sum, msk);
            float alpha = __expf(mi[i] - mnew);
            li[i] = li[i] * alpha + sum;
            mi[i] = mnew;
            o[i][0] *= alpha; o[i][1] *= alpha;
            o[i][2] *= alpha; o[i][3] *= alpha;
            *(float4*)&Ps[(ty * 8 + i) * 64 + tx * 4] = p;
        }
        __syncthreads();

        // O += P . V  (vectorized over j, granules of 4)
#pragma unroll
        for (int J = 0; J < 16; J++) {
            float4 v0 = *(const float4*)&Vs[(J * 4 + 0) * 64 + tx * 4];
            float4 v1 = *(const float4*)&Vs[(J * 4 + 1) * 64 + tx * 4];
            float4 v2 = *(const float4*)&Vs[(J * 4 + 2) * 64 + tx * 4];
            float4 v3 = *(const float4*)&Vs[(J * 4 + 3) * 64 + tx * 4];
#pragma unroll
            for (int i = 0; i < 8; i++) {
                float4 p = *(const float4*)&Ps[(ty * 8 + i) * 64 + (J << 2)];
                o[i][0] = fmaf(p.x, v0.x, o[i][0]);
                o[i][1] = fmaf(p.x, v0.y, o[i][1]);
                o[i][2] = fmaf(p.x, v0.z, o[i][2]);
                o[i][3] = fmaf(p.x, v0.w, o[i][3]);
                o[i][0] = fmaf(p.y, v1.x, o[i][0]);
                o[i][1] = fmaf(p.y, v1.y, o[i][1]);
                o[i][2] = fmaf(p.y, v1.z, o[i][2]);
                o[i][3] = fmaf(p.y, v1.w, o[i][3]);
                o[i][0] = fmaf(p.z, v2.x, o[i][0]);
                o[i][1] = fmaf(p.z, v2.y, o[i][1]);
                o[i][2] = fmaf(p.z, v2.z, o[i][2]);
                o[i][3] = fmaf(p.z, v2.w, o[i][3]);
                o[i][0] = fmaf(p.w, v3.x, o[i][0]);
                o[i][1] = fmaf(p.w, v3.y, o[i][1]);
                o[i][2] = fmaf(p.w, v3.z, o[i][2]);
                o[i][3] = fmaf(p.w, v3.w, o[i][3]);
            }
        }
    }

    // write ctx in [B,N,C] token-major layout
    const int b = bh / NH, h = bh % NH;
#pragma unroll
    for (int i = 0; i < 8; i++) {
        int n = q0 + ty * 8 + i;
        float inv = 1.f / li[i];
        float4 r = make_float4(o[i][0] * inv, o[i][1] * inv,
                               o[i][2] * inv, o[i][3] * inv);
        *(float4*)&g_ctx[(b * SEQ + n) * CH + h * HD + tx * 4] = r;
    }
}

// ---------------------------------------------------------------------------
// Output projection: out[m,c] = sum_k ctx[m,k]*w_proj[c,k] + b_proj[c]
// ---------------------------------------------------------------------------
__global__ __launch_bounds__(256, 2) void proj_gemm_kernel(
    const float* __restrict__ W, const float* __restrict__ bias,
    float* __restrict__ out)
{
    __shared__ float As[128 * 32];
    __shared__ float Bs[128 * 32];
    const int tid = threadIdx.x;
    const int tx = tid & 15, ty = tid >> 4;
    const int m0 = blockIdx.y * 128, c0 = blockIdx.x * 128;

    GEMM_MAINLOOP(g_ctx, W, CH)

    const int c = c0 + tx * 8;
    float4 bv0 = *(const float4*)&bias[c];
    float4 bv1 = *(const float4*)&bias[c + 4];
#pragma unroll
    for (int i = 0; i < 8; i++) {
        int m = m0 + ty * 8 + i;
        float4 r0 = make_float4(acc[i][0] + bv0.x, acc[i][1] + bv0.y,
                                acc[i][2] + bv0.z, acc[i][3] + bv0.w);
        float4 r1 = make_float4(acc[i][4] + bv1.x, acc[i][5] + bv1.y,
                                acc[i][6] + bv1.z, acc[i][7] + bv1.w);
        *(float4*)&out[m * CH + c]     = r0;
        *(float4*)&out[m * CH + c + 4] = r1;
    }
}

// ---------------------------------------------------------------------------
extern "C" void kernel_launch(void* const* d_in, const int* in_sizes, int n_in,
                              void* d_out, int out_size)
{
    const float* x      = (const float*)d_in[0];
    const float* w_qkv  = (const float*)d_in[1];
    const float* w_proj = (const float*)d_in[2];
    const float* b_proj = (const float*)d_in[3];
    float* out = (float*)d_out;

    const int flash_smem = (128*64 + 64*64 + 64*64 + 128*64) * (int)sizeof(float); // 98304 B
    cudaFuncSetAttribute(flash_kernel,
                         cudaFuncAttributeMaxDynamicSharedMemorySize, flash_smem);

    dim3 g1(QKVN / 128, MROWS / 128);   // 18 x 32
    qkv_gemm_kernel<<<g1, 256>>>(x, w_qkv);

    dim3 g2(SEQ / 128, BB * NH);        // 16 x 24
    flash_kernel<<<g2, 256, flash_smem>>>();

    dim3 g3(CH / 128, MROWS / 128);     // 6 x 32
    proj_gemm_kernel<<<g3, 256>>>(w_proj, b_proj, out);
}